// round 1
// baseline (speedup 1.0000x reference)
#include <cuda_runtime.h>
#include <math.h>

#define N_ENT   150000
#define N_USR   60000
#define CDIM    64
#define NE      1000000
#define NNZV    1000000
#define NRELM1  9
#define NHOPS   2

// ---------------- scratch (static device globals; no allocation) ----------------
__device__ float g_ent_cur[(size_t)N_ENT * CDIM];   // 38.4 MB
__device__ float g_usr_cur[(size_t)N_USR * CDIM];   // 15.4 MB
__device__ float g_ent_next[(size_t)N_ENT * CDIM];  // 38.4 MB
__device__ float g_usr_next[(size_t)N_USR * CDIM];  // 15.4 MB
__device__ float g_ew[NE];                          // att -> exp weights
__device__ float g_m[N_ENT];                        // segment max
__device__ float g_s[N_ENT];                        // segment sum

// ---------------- init: cur = emb, out(residual) = emb ----------------
__global__ void k_init(const float* __restrict__ ue,
                       const float* __restrict__ ee,
                       float* __restrict__ out) {
    const int tot_e = N_ENT * CDIM / 4;
    const int tot_u = N_USR * CDIM / 4;
    float4* ec = (float4*)g_ent_cur;
    float4* uc = (float4*)g_usr_cur;
    float4* oe = (float4*)out;
    float4* ou = (float4*)(out + (size_t)N_ENT * CDIM);
    const float4* e4 = (const float4*)ee;
    const float4* u4 = (const float4*)ue;
    int stride = gridDim.x * blockDim.x;
    for (int i = blockIdx.x * blockDim.x + threadIdx.x; i < tot_e; i += stride) {
        float4 v = e4[i]; ec[i] = v; oe[i] = v;
    }
    for (int i = blockIdx.x * blockDim.x + threadIdx.x; i < tot_u; i += stride) {
        float4 v = u4[i]; uc[i] = v; ou[i] = v;
    }
}

// ---------------- zero per-hop accumulators ----------------
__global__ void k_zero() {
    const int tot_e = N_ENT * CDIM / 4;
    const int tot_u = N_USR * CDIM / 4;
    float4 z = make_float4(0.f, 0.f, 0.f, 0.f);
    float4* en = (float4*)g_ent_next;
    float4* un = (float4*)g_usr_next;
    int stride = gridDim.x * blockDim.x;
    int i0 = blockIdx.x * blockDim.x + threadIdx.x;
    for (int i = i0; i < tot_e; i += stride) en[i] = z;
    for (int i = i0; i < tot_u; i += stride) un[i] = z;
    for (int i = i0; i < N_ENT; i += stride) { g_m[i] = 0.f; g_s[i] = 0.f; }
}

// ---------------- pass 1: att per edge + segment max (warp per edge) ----------------
__global__ void k_att(const int* __restrict__ head, const int* __restrict__ tail,
                      const int* __restrict__ etype, const float* __restrict__ weight) {
    int gw = (blockIdx.x * blockDim.x + threadIdx.x) >> 5;
    int lane = threadIdx.x & 31;
    if (gw >= NE) return;
    int h = head[gw];
    int t = tail[gw];
    int r = etype[gw] - 1;
    if (r < 0) r += NRELM1;                 // JAX negative-index wrap: -1 -> 8
    const float2* hp = (const float2*)(g_ent_cur + (size_t)h * CDIM);
    const float2* tp = (const float2*)(g_ent_cur + (size_t)t * CDIM);
    const float2* rp = (const float2*)(weight + (size_t)r * CDIM);
    float2 rv = rp[lane];
    float2 hv = hp[lane];
    float2 tv = tp[lane];
    float a0 = hv.x * rv.x, a1 = hv.y * rv.y;
    float hn = a0 * a0 + a1 * a1;
    float b0 = tv.x * rv.x, b1 = tv.y * rv.y;
    float tn = b0 * b0 + b1 * b1;
    #pragma unroll
    for (int o = 16; o; o >>= 1) {
        hn += __shfl_xor_sync(0xffffffffu, hn, o);
        tn += __shfl_xor_sync(0xffffffffu, tn, o);
    }
    if (lane == 0) {
        float att = hn * tn;                // (|h*r| * |t*r|)^2, always >= 0
        g_ew[gw] = att;
        atomicMax((int*)&g_m[h], __float_as_int(att)); // valid: non-negative floats
    }
}

// ---------------- pass 2: exp + segment sum (thread per edge) ----------------
__global__ void k_exp(const int* __restrict__ head) {
    int e = blockIdx.x * blockDim.x + threadIdx.x;
    if (e >= NE) return;
    int h = head[e];
    float ex = expf(g_ew[e] - g_m[h]);
    g_ew[e] = ex;
    atomicAdd(&g_s[h], ex);
}

// ---------------- pass 3: weighted scatter into entity_next (warp per edge) ----------------
__global__ void k_edge_scatter(const int* __restrict__ head, const int* __restrict__ tail,
                               const int* __restrict__ etype, const float* __restrict__ weight) {
    int gw = (blockIdx.x * blockDim.x + threadIdx.x) >> 5;
    int lane = threadIdx.x & 31;
    if (gw >= NE) return;
    int h = head[gw];
    int t = tail[gw];
    int r = etype[gw] - 1;
    if (r < 0) r += NRELM1;
    float w = g_ew[gw] / g_s[h];            // broadcast load, same addr per warp
    const float2* tp = (const float2*)(g_ent_cur + (size_t)t * CDIM);
    const float2* rp = (const float2*)(weight + (size_t)r * CDIM);
    float2 tv = tp[lane];
    float2 rv = rp[lane];
    float* dst = g_ent_next + (size_t)h * CDIM + lane * 2;
    atomicAdd(dst,     w * tv.x * rv.x);
    atomicAdd(dst + 1, w * tv.y * rv.y);
}

// ---------------- interaction SpMM both directions (warp per nnz) ----------------
__global__ void k_inter(const int* __restrict__ rows, const int* __restrict__ cols,
                        const float* __restrict__ vals) {
    int gw = (blockIdx.x * blockDim.x + threadIdx.x) >> 5;
    int lane = threadIdx.x & 31;
    if (gw >= NNZV) return;
    int row = rows[gw];
    int col = cols[gw];
    float v = vals[gw];
    float2 u = ((const float2*)(g_usr_cur + (size_t)row * CDIM))[lane];
    float2 e = ((const float2*)(g_ent_cur + (size_t)col * CDIM))[lane];
    float* d1 = g_ent_next + (size_t)col * CDIM + lane * 2;
    atomicAdd(d1,     v * u.x);
    atomicAdd(d1 + 1, v * u.y);
    float* d2 = g_usr_next + (size_t)row * CDIM + lane * 2;
    atomicAdd(d2,     v * e.x);
    atomicAdd(d2 + 1, v * e.y);
}

// ---------------- normalize + residual accumulate (warp per row) ----------------
__global__ void k_norm_ent(float* __restrict__ out_res) {
    int row = (blockIdx.x * blockDim.x + threadIdx.x) >> 5;
    int lane = threadIdx.x & 31;
    if (row >= N_ENT) return;
    float2 x = ((const float2*)(g_ent_next + (size_t)row * CDIM))[lane];
    float ss = x.x * x.x + x.y * x.y;
    #pragma unroll
    for (int o = 16; o; o >>= 1) ss += __shfl_xor_sync(0xffffffffu, ss, o);
    float inv = 1.0f / fmaxf(sqrtf(ss), 1e-12f);
    float2 y = make_float2(x.x * inv, x.y * inv);
    ((float2*)(g_ent_cur + (size_t)row * CDIM))[lane] = y;   // becomes next hop's input
    float* o = out_res + (size_t)row * CDIM + lane * 2;
    o[0] += y.x;
    o[1] += y.y;
}

__global__ void k_norm_usr(float* __restrict__ out_res) {
    int row = (blockIdx.x * blockDim.x + threadIdx.x) >> 5;
    int lane = threadIdx.x & 31;
    if (row >= N_USR) return;
    float2 x = ((const float2*)(g_usr_next + (size_t)row * CDIM))[lane];
    float ss = x.x * x.x + x.y * x.y;
    #pragma unroll
    for (int o = 16; o; o >>= 1) ss += __shfl_xor_sync(0xffffffffu, ss, o);
    float inv = 1.0f / fmaxf(sqrtf(ss), 1e-12f);
    float2 y = make_float2(x.x * inv, x.y * inv);
    ((float2*)(g_usr_cur + (size_t)row * CDIM))[lane] = y;
    float* o = out_res + (size_t)row * CDIM + lane * 2;
    o[0] += y.x;
    o[1] += y.y;
}

extern "C" void kernel_launch(void* const* d_in, const int* in_sizes, int n_in,
                              void* d_out, int out_size) {
    const float* user_emb   = (const float*)d_in[0];   // [60000, 64]
    const float* entity_emb = (const float*)d_in[1];   // [150000, 64]
    const float* weight     = (const float*)d_in[2];   // [9, 64]
    const float* inter_vals = (const float*)d_in[3];   // [1M]
    const int*   edge_index = (const int*)d_in[4];     // [2, 1M]: head = +0, tail = +NE
    const int*   edge_type  = (const int*)d_in[5];     // [1M]
    const int*   inter_rows = (const int*)d_in[6];     // [1M]
    const int*   inter_cols = (const int*)d_in[7];     // [1M]
    float* out = (float*)d_out;                        // [ent_res | usr_res]

    const int* head = edge_index;
    const int* tail = edge_index + NE;

    k_init<<<2048, 256>>>(user_emb, entity_emb, out);

    const int WPB = 256;                 // threads per block
    const int edge_warp_blocks = (NE + 7) / 8;         // warp per edge, 8 warps/block
    const int nnz_warp_blocks  = (NNZV + 7) / 8;
    const int exp_blocks       = (NE + WPB - 1) / WPB;
    const int norm_ent_blocks  = (N_ENT + 7) / 8;
    const int norm_usr_blocks  = (N_USR + 7) / 8;

    for (int hop = 0; hop < NHOPS; hop++) {
        k_zero<<<2048, 256>>>();
        k_att<<<edge_warp_blocks, WPB>>>(head, tail, edge_type, weight);
        k_exp<<<exp_blocks, WPB>>>(head);
        k_edge_scatter<<<edge_warp_blocks, WPB>>>(head, tail, edge_type, weight);
        k_inter<<<nnz_warp_blocks, WPB>>>(inter_rows, inter_cols, inter_vals);
        k_norm_ent<<<norm_ent_blocks, WPB>>>(out);
        k_norm_usr<<<norm_usr_blocks, WPB>>>(out + (size_t)N_ENT * CDIM);
    }
}

// round 2
// speedup vs baseline: 1.5979x; 1.5979x over previous
#include <cuda_runtime.h>
#include <math.h>

#define N_ENT   150000
#define N_USR   60000
#define CDIM    64
#define NE      1000000
#define NNZV    1000000
#define NRELM1  9
#define NHOPS   2

// ---------------- scratch (static device globals; no allocation) ----------------
__device__ float g_ent_cur[(size_t)N_ENT * CDIM];   // 38.4 MB
__device__ float g_usr_cur[(size_t)N_USR * CDIM];   // 15.4 MB
__device__ float g_ent_next[(size_t)N_ENT * CDIM];  // 38.4 MB
__device__ float g_usr_next[(size_t)N_USR * CDIM];  // 15.4 MB
__device__ float g_ew[NE];                          // att -> exp weights
__device__ float g_m[N_ENT];                        // segment max
__device__ float g_s[N_ENT];                        // segment sum

// vectorized 128-bit global reduction (sm_90+): one REDG.128 instead of 4 scalar REDG
__device__ __forceinline__ void red_add_v4(float* p, float4 v) {
    asm volatile("red.global.add.v4.f32 [%0], {%1, %2, %3, %4};"
                 :: "l"(p), "f"(v.x), "f"(v.y), "f"(v.z), "f"(v.w)
                 : "memory");
}

// ---------------- init: cur = emb, out(residual) = emb ----------------
__global__ void k_init(const float* __restrict__ ue,
                       const float* __restrict__ ee,
                       float* __restrict__ out) {
    const int tot_e = N_ENT * CDIM / 4;
    const int tot_u = N_USR * CDIM / 4;
    float4* ec = (float4*)g_ent_cur;
    float4* uc = (float4*)g_usr_cur;
    float4* oe = (float4*)out;
    float4* ou = (float4*)(out + (size_t)N_ENT * CDIM);
    const float4* e4 = (const float4*)ee;
    const float4* u4 = (const float4*)ue;
    int stride = gridDim.x * blockDim.x;
    for (int i = blockIdx.x * blockDim.x + threadIdx.x; i < tot_e; i += stride) {
        float4 v = e4[i]; ec[i] = v; oe[i] = v;
    }
    for (int i = blockIdx.x * blockDim.x + threadIdx.x; i < tot_u; i += stride) {
        float4 v = u4[i]; uc[i] = v; ou[i] = v;
    }
}

// ---------------- zero per-hop accumulators ----------------
__global__ void k_zero() {
    const int tot_e = N_ENT * CDIM / 4;
    const int tot_u = N_USR * CDIM / 4;
    float4 z = make_float4(0.f, 0.f, 0.f, 0.f);
    float4* en = (float4*)g_ent_next;
    float4* un = (float4*)g_usr_next;
    int stride = gridDim.x * blockDim.x;
    int i0 = blockIdx.x * blockDim.x + threadIdx.x;
    for (int i = i0; i < tot_e; i += stride) en[i] = z;
    for (int i = i0; i < tot_u; i += stride) un[i] = z;
    for (int i = i0; i < N_ENT; i += stride) { g_m[i] = 0.f; g_s[i] = 0.f; }
}

// ---------------- pass 1: att per edge + segment max (16 lanes/edge, float4) ----------------
__global__ void k_att(const int* __restrict__ head, const int* __restrict__ tail,
                      const int* __restrict__ etype, const float* __restrict__ weight) {
    int idx  = blockIdx.x * blockDim.x + threadIdx.x;
    int e    = idx >> 4;
    int lane = idx & 15;
    if (e >= NE) return;
    int h = head[e];
    int t = tail[e];
    int r = etype[e] - 1;
    if (r < 0) r += NRELM1;                 // JAX negative-index wrap: -1 -> 8
    float4 rv = ((const float4*)(weight    + (size_t)r * CDIM))[lane];
    float4 hv = ((const float4*)(g_ent_cur + (size_t)h * CDIM))[lane];
    float4 tv = ((const float4*)(g_ent_cur + (size_t)t * CDIM))[lane];
    float a0 = hv.x * rv.x, a1 = hv.y * rv.y, a2 = hv.z * rv.z, a3 = hv.w * rv.w;
    float hn = a0 * a0 + a1 * a1 + a2 * a2 + a3 * a3;
    float b0 = tv.x * rv.x, b1 = tv.y * rv.y, b2 = tv.z * rv.z, b3 = tv.w * rv.w;
    float tn = b0 * b0 + b1 * b1 + b2 * b2 + b3 * b3;
    #pragma unroll
    for (int o = 8; o; o >>= 1) {           // reduce within 16-lane group
        hn += __shfl_xor_sync(0xffffffffu, hn, o);
        tn += __shfl_xor_sync(0xffffffffu, tn, o);
    }
    if (lane == 0) {
        float att = hn * tn;                // (|h*r| * |t*r|)^2, always >= 0
        g_ew[e] = att;
        atomicMax((int*)&g_m[h], __float_as_int(att)); // valid: non-negative floats
    }
}

// ---------------- pass 2: exp + segment sum (thread per edge) ----------------
__global__ void k_exp(const int* __restrict__ head) {
    int e = blockIdx.x * blockDim.x + threadIdx.x;
    if (e >= NE) return;
    int h = head[e];
    float ex = expf(g_ew[e] - g_m[h]);
    g_ew[e] = ex;
    atomicAdd(&g_s[h], ex);
}

// ---------------- pass 3: weighted scatter into entity_next (16 lanes/edge, v4 red) ----------------
__global__ void k_edge_scatter(const int* __restrict__ head, const int* __restrict__ tail,
                               const int* __restrict__ etype, const float* __restrict__ weight) {
    int idx  = blockIdx.x * blockDim.x + threadIdx.x;
    int e    = idx >> 4;
    int lane = idx & 15;
    if (e >= NE) return;
    int h = head[e];
    int t = tail[e];
    int r = etype[e] - 1;
    if (r < 0) r += NRELM1;
    float w = g_ew[e] / g_s[h];
    float4 tv = ((const float4*)(g_ent_cur + (size_t)t * CDIM))[lane];
    float4 rv = ((const float4*)(weight    + (size_t)r * CDIM))[lane];
    float4 v = make_float4(w * tv.x * rv.x, w * tv.y * rv.y,
                           w * tv.z * rv.z, w * tv.w * rv.w);
    red_add_v4(g_ent_next + (size_t)h * CDIM + lane * 4, v);
}

// ---------------- interaction SpMM both directions (16 lanes/nnz, v4 red) ----------------
__global__ void k_inter(const int* __restrict__ rows, const int* __restrict__ cols,
                        const float* __restrict__ vals) {
    int idx  = blockIdx.x * blockDim.x + threadIdx.x;
    int nz   = idx >> 4;
    int lane = idx & 15;
    if (nz >= NNZV) return;
    int row = rows[nz];
    int col = cols[nz];
    float v = vals[nz];
    float4 u = ((const float4*)(g_usr_cur + (size_t)row * CDIM))[lane];
    float4 e = ((const float4*)(g_ent_cur + (size_t)col * CDIM))[lane];
    red_add_v4(g_ent_next + (size_t)col * CDIM + lane * 4,
               make_float4(v * u.x, v * u.y, v * u.z, v * u.w));
    red_add_v4(g_usr_next + (size_t)row * CDIM + lane * 4,
               make_float4(v * e.x, v * e.y, v * e.z, v * e.w));
}

// ---------------- normalize + residual accumulate (16 lanes/row, float4) ----------------
__global__ void k_norm_ent(float* __restrict__ out_res) {
    int idx  = blockIdx.x * blockDim.x + threadIdx.x;
    int row  = idx >> 4;
    int lane = idx & 15;
    if (row >= N_ENT) return;
    float4 x = ((const float4*)(g_ent_next + (size_t)row * CDIM))[lane];
    float ss = x.x * x.x + x.y * x.y + x.z * x.z + x.w * x.w;
    #pragma unroll
    for (int o = 8; o; o >>= 1) ss += __shfl_xor_sync(0xffffffffu, ss, o);
    float inv = 1.0f / fmaxf(sqrtf(ss), 1e-12f);
    float4 y = make_float4(x.x * inv, x.y * inv, x.z * inv, x.w * inv);
    ((float4*)(g_ent_cur + (size_t)row * CDIM))[lane] = y;   // next hop's input
    float4* o = (float4*)(out_res + (size_t)row * CDIM) + lane;
    float4 acc = *o;
    acc.x += y.x; acc.y += y.y; acc.z += y.z; acc.w += y.w;
    *o = acc;
}

__global__ void k_norm_usr(float* __restrict__ out_res) {
    int idx  = blockIdx.x * blockDim.x + threadIdx.x;
    int row  = idx >> 4;
    int lane = idx & 15;
    if (row >= N_USR) return;
    float4 x = ((const float4*)(g_usr_next + (size_t)row * CDIM))[lane];
    float ss = x.x * x.x + x.y * x.y + x.z * x.z + x.w * x.w;
    #pragma unroll
    for (int o = 8; o; o >>= 1) ss += __shfl_xor_sync(0xffffffffu, ss, o);
    float inv = 1.0f / fmaxf(sqrtf(ss), 1e-12f);
    float4 y = make_float4(x.x * inv, x.y * inv, x.z * inv, x.w * inv);
    ((float4*)(g_usr_cur + (size_t)row * CDIM))[lane] = y;
    float4* o = (float4*)(out_res + (size_t)row * CDIM) + lane;
    float4 acc = *o;
    acc.x += y.x; acc.y += y.y; acc.z += y.z; acc.w += y.w;
    *o = acc;
}

extern "C" void kernel_launch(void* const* d_in, const int* in_sizes, int n_in,
                              void* d_out, int out_size) {
    const float* user_emb   = (const float*)d_in[0];   // [60000, 64]
    const float* entity_emb = (const float*)d_in[1];   // [150000, 64]
    const float* weight     = (const float*)d_in[2];   // [9, 64]
    const float* inter_vals = (const float*)d_in[3];   // [1M]
    const int*   edge_index = (const int*)d_in[4];     // [2, 1M]: head = +0, tail = +NE
    const int*   edge_type  = (const int*)d_in[5];     // [1M]
    const int*   inter_rows = (const int*)d_in[6];     // [1M]
    const int*   inter_cols = (const int*)d_in[7];     // [1M]
    float* out = (float*)d_out;                        // [ent_res | usr_res]

    const int* head = edge_index;
    const int* tail = edge_index + NE;

    k_init<<<2048, 256>>>(user_emb, entity_emb, out);

    const int WPB = 256;
    const int edge16_blocks = (NE * 16 + WPB - 1) / WPB;     // 16 lanes per edge
    const int nnz16_blocks  = (NNZV * 16 + WPB - 1) / WPB;
    const int exp_blocks    = (NE + WPB - 1) / WPB;
    const int ne16_blocks   = (N_ENT * 16 + WPB - 1) / WPB;
    const int nu16_blocks   = (N_USR * 16 + WPB - 1) / WPB;

    for (int hop = 0; hop < NHOPS; hop++) {
        k_zero<<<2048, 256>>>();
        k_att<<<edge16_blocks, WPB>>>(head, tail, edge_type, weight);
        k_exp<<<exp_blocks, WPB>>>(head);
        k_edge_scatter<<<edge16_blocks, WPB>>>(head, tail, edge_type, weight);
        k_inter<<<nnz16_blocks, WPB>>>(inter_rows, inter_cols, inter_vals);
        k_norm_ent<<<ne16_blocks, WPB>>>(out);
        k_norm_usr<<<nu16_blocks, WPB>>>(out + (size_t)N_ENT * CDIM);
    }
}